// round 1
// baseline (speedup 1.0000x reference)
#include <cuda_runtime.h>
#include <math.h>

#define B        512
#define IN       1024
#define NN       4224
#define TOTAL    5248
#define KB       128
#define NBLK     33
#define OUT_N    128

// Scratch (device globals: allocation-free rule)
__device__ float g_pre[(size_t)B * NN];   // preactivations [row][node]
__device__ float g_h[(size_t)B * KB];     // current block outputs [row][t]

// ---------------------------------------------------------------------------
// Tiled fp32 GEMM:  C[r][jbase+n] (+)= sum_k A[r][k] * Wsub[n*TOTAL + k]
// M=512 fixed, BM=BN=64, BK=16, 256 threads, 4x4 microtile.
// asel: 0 -> A = Aparam (x), 1 -> A = g_h.
// All dims are multiples of tile sizes (checked statically by construction).
// ---------------------------------------------------------------------------
#define BM 64
#define BN 64
#define BK 16

__global__ void gemm_kernel(const float* __restrict__ Aparam, int lda,
                            const float* __restrict__ Wsub,
                            int jbase, int kc, int accum, int asel)
{
    __shared__ float As[BK][BM];
    __shared__ float Bs[BK][BN];

    const float* A = asel ? g_h : Aparam;

    int m0 = blockIdx.x * BM;
    int n0 = blockIdx.y * BN;
    int tid = threadIdx.x;
    int tx = tid & 15;          // 0..15 (n dir)
    int ty = tid >> 4;          // 0..15 (m dir)

    int lr = tid >> 2;          // 0..63
    int lk = (tid & 3) * 4;     // 0,4,8,12

    float acc[4][4];
#pragma unroll
    for (int i = 0; i < 4; i++)
#pragma unroll
        for (int j = 0; j < 4; j++) acc[i][j] = 0.0f;

    for (int kk = 0; kk < kc; kk += BK) {
        float4 av = *(const float4*)(A + (size_t)(m0 + lr) * lda + kk + lk);
        As[lk + 0][lr] = av.x;
        As[lk + 1][lr] = av.y;
        As[lk + 2][lr] = av.z;
        As[lk + 3][lr] = av.w;

        float4 bv = *(const float4*)(Wsub + (size_t)(n0 + lr) * TOTAL + kk + lk);
        Bs[lk + 0][lr] = bv.x;
        Bs[lk + 1][lr] = bv.y;
        Bs[lk + 2][lr] = bv.z;
        Bs[lk + 3][lr] = bv.w;

        __syncthreads();

#pragma unroll
        for (int k = 0; k < BK; k++) {
            float a[4], b[4];
            *(float4*)a = *(const float4*)&As[k][ty * 4];
            *(float4*)b = *(const float4*)&Bs[k][tx * 4];
#pragma unroll
            for (int mm = 0; mm < 4; mm++)
#pragma unroll
                for (int nn = 0; nn < 4; nn++)
                    acc[mm][nn] += a[mm] * b[nn];
        }
        __syncthreads();
    }

#pragma unroll
    for (int mm = 0; mm < 4; mm++) {
        float* cp = g_pre + (size_t)(m0 + ty * 4 + mm) * NN + jbase + n0 + tx * 4;
        if (accum) {
#pragma unroll
            for (int nn = 0; nn < 4; nn++) cp[nn] += acc[mm][nn];
        } else {
            float4 v;
            v.x = acc[mm][0]; v.y = acc[mm][1]; v.z = acc[mm][2]; v.w = acc[mm][3];
            *(float4*)cp = v;
        }
    }
}

// ---------------------------------------------------------------------------
// In-block sequential recurrence. One warp per batch row (grid 64 x 256thr =
// 512 warps = 512 rows). Each lane owns 4 nodes of the 128-node block
// (node = lane + 32q). Rank-1 update formulation: after h_t is known, every
// lane updates its still-pending partial preactivations; the critical path
// per step is tanh -> shfl -> one FMA.
// Dynamic smem: ws[t*129 + i] = W[j0+i][IN+j0+t]  (128x129 floats, padded).
// ---------------------------------------------------------------------------
__global__ void seq_kernel(const float* __restrict__ W,
                           float* __restrict__ out, int b)
{
    extern __shared__ float ws[];  // 128*129 floats = 66048 B

    int tid  = threadIdx.x;        // 256
    int lane = tid & 31;
    int row  = blockIdx.x * 8 + (tid >> 5);
    int j0   = b * KB;

    // Stage the block's triangular weight tile into smem.
    // ws layout [t][i] (stride 129) -> step-t reads ws[t*129 + node] are
    // conflict-free and broadcast across warps.
    const float* Wt = W + (size_t)j0 * TOTAL + IN + j0;
    for (int idx = tid; idx < KB * KB; idx += 256) {
        int i = idx >> 7;      // weight row (node within block)
        int t = idx & 127;     // parent within block
        ws[t * 129 + i] = Wt[(size_t)i * TOTAL + t];
    }
    __syncthreads();

    float p[4];
#pragma unroll
    for (int q = 0; q < 4; q++)
        p[q] = g_pre[(size_t)row * NN + j0 + lane + 32 * q];

    const bool isOut = (b == NBLK - 1);
    float* ghrow = g_h + (size_t)row * KB;
    float* orow  = out + (size_t)row * OUT_N;

#pragma unroll
    for (int slot = 0; slot < 4; slot++) {
#pragma unroll 4
        for (int t2 = 0; t2 < 32; t2++) {
            int t = slot * 32 + t2;

            // tanh(p) = (e-1)/(e+1), e = exp(2p). Exact identity; __expf
            // rel-err ~1e-7 and residual cancellation only hurts abs error
            // near zero (harmless downstream).
            float e  = __expf(2.0f * p[slot]);
            float hv = 1.0f - 2.0f / (e + 1.0f);
            float h  = __shfl_sync(0xffffffffu, hv, t2);

            if (lane == t2) {
                ghrow[t] = h;
                if (isOut) orow[t] = 1.0f / (1.0f + __expf(-h));
            }

            const float* wst = ws + t * 129;
#pragma unroll
            for (int q = 0; q < 4; q++) {
                int node = lane + 32 * q;
                float w = wst[node];
                if (node > t) p[q] += h * w;
            }
        }
    }
}

// ---------------------------------------------------------------------------
extern "C" void kernel_launch(void* const* d_in, const int* in_sizes, int n_in,
                              void* d_out, int out_size)
{
    const float* x = (const float*)d_in[0];   // [512][1024]
    const float* W = (const float*)d_in[1];   // [4224][5248]
    float* out = (float*)d_out;               // [512][128]

    (void)in_sizes; (void)n_in; (void)out_size;

    // seq_kernel needs 66048 B dynamic smem (> 48 KB default).
    cudaFuncSetAttribute(seq_kernel,
                         cudaFuncAttributeMaxDynamicSharedMemorySize, 66048);

    // Phase A: pre = x @ W[:, :1024]^T    (writes all of g_pre)
    gemm_kernel<<<dim3(8, NN / BN), 256>>>(x, IN, W, /*jbase=*/0,
                                           /*kc=*/IN, /*accum=*/0, /*asel=*/0);

    for (int b = 0; b < NBLK; b++) {
        // Resolve the 128-step in-block recurrence (writes g_h, and the
        // final block writes sigmoid outputs).
        seq_kernel<<<64, 256, 66048>>>(W, out, b);

        if (b < NBLK - 1) {
            // Rank-128 update: pre[:, jbase:] += g_h @ W[jbase:, cols]^T
            int jbase = (b + 1) * KB;
            int nrem  = NN - jbase;               // multiple of 128
            const float* Wsub = W + (size_t)jbase * TOTAL + (IN + b * KB);
            gemm_kernel<<<dim3(8, nrem / BN), 256>>>(nullptr, KB, Wsub,
                                                     jbase, KB, /*accum=*/1,
                                                     /*asel=*/1);
        }
    }
}